// round 8
// baseline (speedup 1.0000x reference)
#include <cuda_runtime.h>
#include <cstdint>

#define S_NUM 16      // samples
#define F_NUM 16      // frames
#define FS 128        // frame size
#define PLANE (FS*FS) // 16384

// Scratch in event-friendly layout [F, Y, X, S, 2] : 16*16384*32 floats = 32 MB.
// Zero-initialized at module load; transpose_kernel re-zeroes it every call,
// so it is zero at entry of every kernel_launch execution (incl. graph replays).
__device__ float g_scratch[(size_t)F_NUM * PLANE * S_NUM * 2];

// Scatter: one thread per event; all 16 samples' (neg,pos) pairs land in 32
// consecutive floats of scratch -> 8 float4 vector atomics (RED.E.ADD.F32x4).
// Index dtype (int32 vs int64) is detected inline per block: for int64 (LE,
// values < 2^31) the odd 32-bit words of the x-row are all zero; for int32
// they are random y-values in [0,128). 8 probes -> P(misdetect) = 128^-8.
__global__ __launch_bounds__(256)
void scatter_kernel(const float* __restrict__ vals,
                    const int32_t* __restrict__ idx32,
                    int N, int W)
{
    __shared__ int s_idx64;
    if (threadIdx.x == 0) {
        int allz = 1;
        #pragma unroll
        for (int k = 0; k < 8; k++) {
            if (idx32[2LL * N + 2 * k + 1] != 0) { allz = 0; break; }
        }
        s_idx64 = allz;            // L2-broadcast hits; identical in every block
    }
    __syncthreads();

    const int n = blockIdx.x * blockDim.x + threadIdx.x;
    if (n >= N) return;

    int x, y;
    if (s_idx64) {
        const long long* idx64 = (const long long*)idx32;
        x = (int)idx64[(long long)N + n];
        y = (int)idx64[2LL * N + n];
    } else {
        x = idx32[N + n];
        y = idx32[2 * N + n];
    }

    const int f = (blockIdx.x * blockDim.x) / W;   // uniform per block (W%256==0)

    // base for (f, y, x, s=0, p=0); 128B-aligned.
    float4* base = (float4*)(g_scratch +
        ((size_t)f * PLANE + (size_t)y * FS + x) * (S_NUM * 2));

    #pragma unroll
    for (int k = 0; k < 8; k++) {
        const float v0 = vals[(size_t)(2 * k)     * N + n];
        const float v1 = vals[(size_t)(2 * k + 1) * N + n];
        float4 u;
        u.x = fmaxf(-v0, 0.0f);   // neg, sample 2k
        u.y = fmaxf( v0, 0.0f);   // pos, sample 2k
        u.z = fmaxf(-v1, 0.0f);   // neg, sample 2k+1
        u.w = fmaxf( v1, 0.0f);   // pos, sample 2k+1
        atomicAdd(base + k, u);   // RED.E.ADD.F32x4 (sm_90+)
    }
}

// Transpose scratch [F, pos, sp] (pos = y*FS+x flat, sp = s*2+p)
//            -> out [F, s, p, pos].  Tile: 64 positions x 32 sp = 8 KB smem.
// Also re-zeroes the scratch region it consumed (restores the invariant that
// scratch is zero at the start of the next kernel_launch execution).
__global__ __launch_bounds__(256)
void transpose_kernel(float* __restrict__ out)
{
    __shared__ float tile[64][33];   // pad to kill bank conflicts

    const int f  = blockIdx.x >> 8;          // 256 tiles per frame
    const int p0 = (blockIdx.x & 255) * 64;  // first flat position of tile
    const int t  = threadIdx.x;

    float4* src = (float4*)(g_scratch + ((size_t)f * PLANE + p0) * (S_NUM * 2));
    const float4 zero4 = make_float4(0.f, 0.f, 0.f, 0.f);

    // Load 64*32 floats coalesced as float4 (512 float4s, 2 per thread),
    // then zero exactly what we read (read-before-write within the thread).
    #pragma unroll
    for (int r = 0; r < 2; r++) {
        const int j = r * 256 + t;           // float4 index 0..511
        const float4 v = src[j];
        src[j] = zero4;                      // re-zero scratch for next run
        const int fi  = j * 4;               // flat float index
        const int pos = fi >> 5;             // /32
        const int sp  = fi & 31;
        tile[pos][sp]     = v.x;
        tile[pos][sp + 1] = v.y;
        tile[pos][sp + 2] = v.z;
        tile[pos][sp + 3] = v.w;
    }
    __syncthreads();

    // Write: for each sp, 64 consecutive positions -> coalesced 256B rows.
    #pragma unroll
    for (int r = 0; r < 8; r++) {
        const int e   = r * 256 + t;         // 0..2047
        const int sp  = e >> 6;              // /64
        const int pos = e & 63;
        // out[((f*S + s)*2 + p)*PLANE + p0 + pos], sp = s*2+p
        out[((size_t)f * (S_NUM * 2) + sp) * PLANE + p0 + pos] = tile[pos][sp];
    }
}

extern "C" void kernel_launch(void* const* d_in, const int* in_sizes, int n_in,
                              void* d_out, int out_size)
{
    const float*   vals = (const float*)d_in[0];
    const int32_t* idx  = (const int32_t*)d_in[1];
    float*         out  = (float*)d_out;

    const int N = in_sizes[0] / S_NUM;     // 1048576 events
    const int W = N / F_NUM;               // 65536 events per frame

    const int threads = 256;
    scatter_kernel<<<(N + threads - 1) / threads, threads>>>(vals, idx, N, W);

    // Transpose writes every output element (no out memset needed) and
    // re-zeroes scratch (no scratch memset needed).
    transpose_kernel<<<F_NUM * (PLANE / 64), 256>>>(out);
}